// round 14
// baseline (speedup 1.0000x reference)
#include <cuda_runtime.h>
#include <cuda_bf16.h>
#include <math.h>
#include <stdint.h>

// ---------------- problem constants ----------------
#define B_    4
#define IMG_H 1024
#define IMG_W 1536

#define H1 512
#define W1 768
#define H2 256
#define W2 384
#define H3 128
#define W3 192
#define HF 64
#define WF 96

#define C1 32
#define C2 64
#define C3 128
#define C4 128

#define OUTC  64
#define DBINS 16
#define NYV 256
#define NXV 256
#define SV  (NYV*NXV)

// ---------------- scratch (static device globals; no allocation) ----------------
__device__ float g_im[(size_t)B_ * IMG_H * IMG_W * 4];   // NHWC padded C=4
__device__ float g_x1[(size_t)B_ * H1 * W1 * C1];
__device__ float g_x2[(size_t)B_ * H2 * W2 * C2];
__device__ float g_x3[(size_t)B_ * H3 * W3 * C3];
__device__ float g_x4[(size_t)B_ * HF * WF * C4];
__device__ float g_fh[(size_t)B_ * HF * WF * C4];
__device__ float g_canvas[(size_t)B_ * SV * OUTC];
__device__ float g_wacc[B_ * SV];

__device__ float g_wt1[36 * 32];
// gemm-layer B images: [chunk][oc][32] fp32
__device__ float g_wb2[9  * 64  * 32];
__device__ float g_wb3[18 * 128 * 32];
__device__ float g_wb4[36 * 128 * 32];
__device__ float g_wb5[36 * 128 * 32];

// ---------------- packed f32x2 helpers ----------------
__device__ __forceinline__ uint64_t pk2(float lo, float hi) {
    uint64_t r;
    asm("mov.b64 %0, {%1, %2};" : "=l"(r) : "f"(lo), "f"(hi));
    return r;
}
__device__ __forceinline__ void upk2(uint64_t v, float& lo, float& hi) {
    asm("mov.b64 {%0, %1}, %2;" : "=f"(lo), "=f"(hi) : "l"(v));
}
#define FMA2(d, a, b, c) \
    asm("fma.rn.f32x2 %0, %1, %2, %3;" : "=l"(d) : "l"(a), "l"(b), "l"(c))

// ---------------- zero canvas ----------------
__global__ void zero_kernel() {
    int n1 = B_ * SV * OUTC;
    int n2 = B_ * SV;
    for (int i = blockIdx.x * blockDim.x + threadIdx.x; i < n1; i += gridDim.x * blockDim.x)
        g_canvas[i] = 0.f;
    for (int i = blockIdx.x * blockDim.x + threadIdx.x; i < n2; i += gridDim.x * blockDim.x)
        g_wacc[i] = 0.f;
}

// ---------------- conv1 weight transpose ----------------
__global__ void wprep1(const float* __restrict__ w) {
    int i = blockIdx.x * blockDim.x + threadIdx.x;
    if (i >= 36 * 32) return;
    int oc = i % 32;
    int k  = i / 32;
    int tap = k / 4;
    int ic  = k % 4;
    g_wt1[i] = (ic < 3) ? w[(oc * 3 + ic) * 9 + tap] : 0.f;
}

// ---------------- gemm-layer weight prep: [chunk][oc][32] fp32 ----------------
__global__ void wprep_mma(const float* __restrict__ w, float* __restrict__ out,
                          int CIN, int OC, int NCH) {
    int i = blockIdx.x * blockDim.x + threadIdx.x;
    if (i >= NCH * OC * 32) return;
    int j  = i & 31;
    int oc = (i >> 5) % OC;
    int ch = i / (OC * 32);
    int kg = ch * 32 + j;
    int tap = kg / CIN;
    int ic  = kg % CIN;
    out[i] = w[(oc * CIN + ic) * 9 + tap];
}

// ---------------- images NCHW -> NHWC padded C=4 ----------------
__global__ void im2nhwc(const float* __restrict__ im) {
    int i = blockIdx.x * blockDim.x + threadIdx.x;
    const int HW = IMG_H * IMG_W;
    if (i >= B_ * HW) return;
    int b = i / HW;
    int p = i % HW;
    const float* base = im + (size_t)b * 3 * HW + p;
    float4 v;
    v.x = base[0];
    v.y = base[HW];
    v.z = base[2 * HW];
    v.w = 0.f;
    *(float4*)&g_im[(size_t)i * 4] = v;
}

// ---------------- conv1: direct fp32 ----------------
__global__ __launch_bounds__(256) void conv1_kernel(const float* __restrict__ sc,
                                                    const float* __restrict__ bi) {
    __shared__ float ws[36 * 32];
    __shared__ float ssc[32], sbi[32];
    int tid = threadIdx.x;
    for (int i = tid; i < 36 * 32; i += 256) ws[i] = g_wt1[i];
    if (tid < 32) { ssc[tid] = sc[tid]; sbi[tid] = bi[tid]; }
    __syncthreads();

    int p = blockIdx.x * 256 + tid;
    const int HW = H1 * W1;
    int b  = p / HW;
    int r  = p % HW;
    int oh = r / W1;
    int ow = r % W1;
    int ihb = oh * 2 - 1;
    int iwb = ow * 2 - 1;

    float4 patch[9];
    #pragma unroll
    for (int t = 0; t < 9; t++) {
        int kh = t / 3, kw = t % 3;
        int ih = ihb + kh, iw = iwb + kw;
        float4 v = make_float4(0.f, 0.f, 0.f, 0.f);
        if ((unsigned)ih < (unsigned)IMG_H && (unsigned)iw < (unsigned)IMG_W)
            v = *(const float4*)&g_im[(((size_t)b * IMG_H + ih) * IMG_W + iw) * 4];
        patch[t] = v;
    }

    float4 acc[8];
    #pragma unroll
    for (int q = 0; q < 8; q++) acc[q] = make_float4(0.f, 0.f, 0.f, 0.f);

    #pragma unroll
    for (int t = 0; t < 9; t++) {
        #pragma unroll
        for (int ic = 0; ic < 4; ic++) {
            float a = (ic == 0) ? patch[t].x : (ic == 1) ? patch[t].y :
                      (ic == 2) ? patch[t].z : patch[t].w;
            int k = t * 4 + ic;
            #pragma unroll
            for (int q = 0; q < 8; q++) {
                float4 wv = ((float4*)ws)[k * 8 + q];
                acc[q].x += a * wv.x;
                acc[q].y += a * wv.y;
                acc[q].z += a * wv.z;
                acc[q].w += a * wv.w;
            }
        }
    }

    float* outp = &g_x1[(size_t)p * C1];
    #pragma unroll
    for (int q = 0; q < 8; q++) {
        float4 v;
        v.x = fmaxf(acc[q].x * ssc[q * 4 + 0] + sbi[q * 4 + 0], 0.f);
        v.y = fmaxf(acc[q].y * ssc[q * 4 + 1] + sbi[q * 4 + 1], 0.f);
        v.z = fmaxf(acc[q].z * ssc[q * 4 + 2] + sbi[q * 4 + 2], 0.f);
        v.w = fmaxf(acc[q].w * ssc[q * 4 + 3] + sbi[q * 4 + 3], 0.f);
        *(float4*)&outp[q * 4] = v;
    }
}

// ---------------- fp32x2 implicit-GEMM conv: transposed A tile, packed dual-FMA ----------
// BM=128 pix, BN=64 oc, BK=32. 256 threads, thread tile 8 pix x 4 oc (4 pix-pairs).
// As[k][pix] stride 132 (conflict-free via row=tid&127), Bs[k][oc] stride 68 (bo=tid&63).
#define A_CH (32 * 132)      // floats per A chunk buffer
#define B_CH (32 * 68)       // floats per B chunk buffer
#define SMEMB ((2 * A_CH + 2 * B_CH) * 4)   // 51200 bytes

template <int CIN, int OC, int S, int H, int W, int OH, int OW>
__global__ __launch_bounds__(256)
void conv_gemm3(const float* __restrict__ in, const float* __restrict__ wb,
                const float* __restrict__ sc, const float* __restrict__ bi,
                float* __restrict__ out)
{
    constexpr int NCH = 9 * CIN / 32;

    extern __shared__ float smf[];
    float* As = smf;                 // [2][32][132]
    float* Bs = smf + 2 * A_CH;      // [2][32][68]

    const int tid = threadIdx.x;
    const int pix0 = blockIdx.x * 128;
    const int oc0  = blockIdx.y * 64;

    // A-load mapping: row = tid&127 (one pixel per thread), seg = (tid>>7)*16 k's
    const int row = tid & 127;
    const int seg = (tid >> 7) * 16;
    int p = pix0 + row;
    int b = p / (OH * OW);
    int r = p % (OH * OW);
    int oh = r / OW;
    int ow = r % OW;
    const int ihb = oh * S - 1;
    const int iwb = ow * S - 1;

    // B-load mapping: bo = tid&63 (oc row), kq = (tid>>6 & 1)*... use tid>>6: 0..3
    // threads 0..63 -> (bo, k 0..7), 64..127 -> (bo, k 8..15), etc.
    const int bo = tid & 63;
    const int kq = (tid >> 6) * 8;

    // compute mapping: tn = tid&15 (oc group of 4), tm = tid>>4 (pix group of 8)
    const int tn = tid & 15;
    const int tm = tid >> 4;

    uint64_t accp[4][4];             // [pix-pair][oc]
    #pragma unroll
    for (int q = 0; q < 4; q++)
        #pragma unroll
        for (int j = 0; j < 4; j++) accp[q][j] = 0ull;

    float4 aR[4];
    float4 bR[2];

    auto loadg = [&](int c) {
        int kg0 = c * 32 + seg;
        int tap = kg0 / CIN;
        int ic0 = kg0 % CIN;
        int ih = ihb + tap / 3;
        int iw = iwb + tap % 3;
        bool valid = ((unsigned)ih < (unsigned)H) && ((unsigned)iw < (unsigned)W);
        if (valid) {
            const float4* src = (const float4*)(in + ((size_t)(b * H + ih) * W + iw) * CIN + ic0);
            #pragma unroll
            for (int g = 0; g < 4; g++) aR[g] = src[g];
        } else {
            #pragma unroll
            for (int g = 0; g < 4; g++) aR[g] = make_float4(0.f, 0.f, 0.f, 0.f);
        }
        const float4* bsrc = (const float4*)(wb + ((size_t)c * OC + oc0 + bo) * 32 + kq);
        bR[0] = bsrc[0];
        bR[1] = bsrc[1];
    };

    auto store_s = [&](int buf) {
        float* Ab = As + buf * A_CH;
        #pragma unroll
        for (int g = 0; g < 4; g++) {
            Ab[(seg + g * 4 + 0) * 132 + row] = aR[g].x;
            Ab[(seg + g * 4 + 1) * 132 + row] = aR[g].y;
            Ab[(seg + g * 4 + 2) * 132 + row] = aR[g].z;
            Ab[(seg + g * 4 + 3) * 132 + row] = aR[g].w;
        }
        float* Bb = Bs + buf * B_CH;
        Bb[(kq + 0) * 68 + bo] = bR[0].x;
        Bb[(kq + 1) * 68 + bo] = bR[0].y;
        Bb[(kq + 2) * 68 + bo] = bR[0].z;
        Bb[(kq + 3) * 68 + bo] = bR[0].w;
        Bb[(kq + 4) * 68 + bo] = bR[1].x;
        Bb[(kq + 5) * 68 + bo] = bR[1].y;
        Bb[(kq + 6) * 68 + bo] = bR[1].z;
        Bb[(kq + 7) * 68 + bo] = bR[1].w;
    };

    loadg(0);
    store_s(0);
    __syncthreads();

    for (int c = 0; c < NCH; c++) {
        const int buf = c & 1;
        if (c + 1 < NCH) loadg(c + 1);

        const float* Ab = As + buf * A_CH + tm * 8;
        const float* Bb = Bs + buf * B_CH + tn * 4;

        #pragma unroll
        for (int k = 0; k < 32; k++) {
            // A: 8 contiguous pixels = 4 packed pairs via 2x LDS.128
            ulonglong2 a01 = *(const ulonglong2*)&Ab[k * 132];
            ulonglong2 a23 = *(const ulonglong2*)&Ab[k * 132 + 4];
            // B: 4 oc scalars, splat to pairs
            float4 b4 = *(const float4*)&Bb[k * 68];
            uint64_t bs0 = pk2(b4.x, b4.x);
            uint64_t bs1 = pk2(b4.y, b4.y);
            uint64_t bs2 = pk2(b4.z, b4.z);
            uint64_t bs3 = pk2(b4.w, b4.w);
            FMA2(accp[0][0], a01.x, bs0, accp[0][0]);
            FMA2(accp[0][1], a01.x, bs1, accp[0][1]);
            FMA2(accp[0][2], a01.x, bs2, accp[0][2]);
            FMA2(accp[0][3], a01.x, bs3, accp[0][3]);
            FMA2(accp[1][0], a01.y, bs0, accp[1][0]);
            FMA2(accp[1][1], a01.y, bs1, accp[1][1]);
            FMA2(accp[1][2], a01.y, bs2, accp[1][2]);
            FMA2(accp[1][3], a01.y, bs3, accp[1][3]);
            FMA2(accp[2][0], a23.x, bs0, accp[2][0]);
            FMA2(accp[2][1], a23.x, bs1, accp[2][1]);
            FMA2(accp[2][2], a23.x, bs2, accp[2][2]);
            FMA2(accp[2][3], a23.x, bs3, accp[2][3]);
            FMA2(accp[3][0], a23.y, bs0, accp[3][0]);
            FMA2(accp[3][1], a23.y, bs1, accp[3][1]);
            FMA2(accp[3][2], a23.y, bs2, accp[3][2]);
            FMA2(accp[3][3], a23.y, bs3, accp[3][3]);
        }

        if (c + 1 < NCH) {
            store_s((c + 1) & 1);
            __syncthreads();
        }
    }
    __syncthreads();

    // ---- epilogue: unpack pairs, stage in smem, scale+bias+relu, coalesced store ----
    float* osm = smf;                 // [128][68]
    #pragma unroll
    for (int q = 0; q < 4; q++) {
        float4 v0, v1;
        upk2(accp[q][0], v0.x, v1.x);
        upk2(accp[q][1], v0.y, v1.y);
        upk2(accp[q][2], v0.z, v1.z);
        upk2(accp[q][3], v0.w, v1.w);
        *(float4*)&osm[(tm * 8 + 2 * q + 0) * 68 + tn * 4] = v0;
        *(float4*)&osm[(tm * 8 + 2 * q + 1) * 68 + tn * 4] = v1;
    }
    __syncthreads();

    {
        const int orow = tid >> 1;
        const int oseg = (tid & 1) * 32;
        float vv[32];
        #pragma unroll
        for (int i = 0; i < 32; i++) {
            int oc = oc0 + oseg + i;
            vv[i] = fmaxf(osm[orow * 68 + oseg + i] * __ldg(&sc[oc]) + __ldg(&bi[oc]), 0.f);
        }
        float4* dst = (float4*)(out + (size_t)(pix0 + orow) * OC + oc0 + oseg);
        #pragma unroll
        for (int q = 0; q < 8; q++) dst[q] = ((float4*)vv)[q];
    }
}

// ---------------- heads + depth lift + backprojection + gaussian splat ----------------
__global__ void heads_splat(const float* __restrict__ x4, const float* __restrict__ fh,
                            const float* __restrict__ fw2, const float* __restrict__ fb2,
                            const float* __restrict__ dw,  const float* __restrict__ db,
                            const float* __restrict__ oww, const float* __restrict__ ob,
                            const float* __restrict__ camK, const float* __restrict__ Tlc,
                            const int* __restrict__ imgh, const int* __restrict__ imgw)
{
    const int pix = blockIdx.x;
    const int w   = pix % WF;
    int t = pix / WF;
    const int h = t % HF;
    const int b = t / HF;
    const int tid = threadIdx.x;

    __shared__ float sx4[C4];
    __shared__ float sfh[C4];
    __shared__ float sfeat[OUTC];
    __shared__ float sdl[DBINS];
    __shared__ float sprm[4];

    sx4[tid] = x4[(size_t)pix * C4 + tid];
    sfh[tid] = fh[(size_t)pix * C4 + tid];
    __syncthreads();

    if (tid < OUTC) {
        float a = 0.f;
        const float* wr = fw2 + tid * C4;
        #pragma unroll 8
        for (int k = 0; k < C4; k++) a += wr[k] * sfh[k];
        sfeat[tid] = a + fb2[tid];
    } else if (tid < OUTC + DBINS) {
        int d = tid - OUTC;
        float a = 0.f;
        const float* wr = dw + d * C4;
        #pragma unroll 8
        for (int k = 0; k < C4; k++) a += wr[k] * sx4[k];
        sdl[d] = a + db[d];
    } else if (tid == OUTC + DBINS) {
        float a = 0.f;
        #pragma unroll 8
        for (int k = 0; k < C4; k++) a += oww[k] * sx4[k];
        sprm[0] = 1.f / (1.f + expf(-(a + ob[0])));
    }
    __syncthreads();

    if (tid == 0) {
        float m = -1e30f;
        #pragma unroll
        for (int d = 0; d < DBINS; d++) m = fmaxf(m, sdl[d]);
        float sum = 0.f, zz = 0.f;
        #pragma unroll
        for (int d = 0; d < DBINS; d++) {
            float e = expf(sdl[d] - m);
            sum += e;
            zz  += e * (1.f + (float)d * (59.f / 15.f));
        }
        float z = zz / sum;

        float ihf = (float)imgh[0];
        float iwf = (float)imgw[0];
        float ys = ((float)h + 0.5f) * (ihf / (float)HF);
        float xs = ((float)w + 0.5f) * (iwf / (float)WF);

        const float* K = camK + b * 9;
        float fx = fmaxf(K[0], 1e-6f), fy = fmaxf(K[4], 1e-6f);
        float cx = K[2], cy = K[5];
        float xc = (xs - cx) * z / fx;
        float yc = (ys - cy) * z / fy;

        const float* T = Tlc + b * 16;
        float lx = T[0] * xc + T[1] * yc + T[2]  * z + T[3];
        float ly = T[4] * xc + T[5] * yc + T[6]  * z + T[7];
        float lz = T[8] * xc + T[9] * yc + T[10] * z + T[11];

        int xi = (int)floorf((lx + 51.2f) * 2.5f);
        int yi = (int)floorf((ly + 51.2f) * 2.5f);
        bool inb = (xi >= 0) && (xi < NXV) && (yi >= 0) && (yi < NYV) &&
                   (lz >= -5.f) && (lz < 3.f);
        float op = sprm[0];
        float bw = (op >= 0.05f && inb) ? op : 0.f;
        sprm[1] = bw;
        sprm[2] = __int_as_float(xi);
        sprm[3] = __int_as_float(yi);
    }
    __syncthreads();

    float bw = sprm[1];
    if (bw <= 0.f) return;
    int xi = __float_as_int(sprm[2]);
    int yi = __float_as_int(sprm[3]);

    #pragma unroll
    for (int tap = 0; tap < 9; tap++) {
        int dy = tap / 3 - 1;
        int dx = tap % 3 - 1;
        int ty = yi + dy;
        int tx = xi + dx;
        if ((unsigned)tx >= (unsigned)NXV || (unsigned)ty >= (unsigned)NYV) continue;
        float kwv = expf(-(float)(dx * dx + dy * dy) * (1.f / 1.28f));
        float sw = bw * kwv;
        int vox = b * SV + ty * NXV + tx;
        if (tid < OUTC) atomicAdd(&g_canvas[(size_t)vox * OUTC + tid], sfeat[tid] * sw);
        if (tid == OUTC) atomicAdd(&g_wacc[vox], sw);
    }
}

// ---------------- normalize + transpose (pix, C) -> (B, C, NY, NX) ----------------
__global__ void finalize_kernel(float* __restrict__ out)
{
    __shared__ float tile[OUTC][33];
    int gp  = blockIdx.x * 32;
    int tid = threadIdx.x;

    for (int i = tid; i < 32 * OUTC; i += 256) {
        int p = i >> 6;
        int c = i & 63;
        float wv  = g_wacc[gp + p];
        float inv = (wv > 0.f) ? (1.f / fmaxf(wv, 1e-6f)) : 0.f;
        tile[c][p] = g_canvas[(size_t)(gp + p) * OUTC + c] * inv;
    }
    __syncthreads();

    int b  = gp >> 16;
    int p0 = gp & 65535;
    for (int i = tid; i < OUTC * 32; i += 256) {
        int c = i >> 5;
        int x = i & 31;
        out[(((b * OUTC) + c) << 16) + p0 + x] = tile[c][x];
    }
}

// ---------------- launch ----------------
extern "C" void kernel_launch(void* const* d_in, const int* in_sizes, int n_in,
                              void* d_out, int out_size)
{
    const float* images = (const float*)d_in[0];
    const float* camK   = (const float*)d_in[1];
    const float* Tlc    = (const float*)d_in[2];
    const float* w1 = (const float*)d_in[3];
    const float* s1 = (const float*)d_in[4];
    const float* b1 = (const float*)d_in[5];
    const float* w2 = (const float*)d_in[6];
    const float* s2 = (const float*)d_in[7];
    const float* b2 = (const float*)d_in[8];
    const float* w3 = (const float*)d_in[9];
    const float* s3 = (const float*)d_in[10];
    const float* b3 = (const float*)d_in[11];
    const float* w4 = (const float*)d_in[12];
    const float* s4 = (const float*)d_in[13];
    const float* b4 = (const float*)d_in[14];
    const float* fw1 = (const float*)d_in[15];
    const float* fs1 = (const float*)d_in[16];
    const float* fb1 = (const float*)d_in[17];
    const float* fw2 = (const float*)d_in[18];
    const float* fb2 = (const float*)d_in[19];
    const float* dw  = (const float*)d_in[20];
    const float* db  = (const float*)d_in[21];
    const float* ow  = (const float*)d_in[22];
    const float* ob  = (const float*)d_in[23];
    const int* imgh  = (const int*)d_in[24];
    const int* imgw  = (const int*)d_in[25];
    float* out = (float*)d_out;

    float* x1;  cudaGetSymbolAddress((void**)&x1,  g_x1);
    float* x2;  cudaGetSymbolAddress((void**)&x2,  g_x2);
    float* x3;  cudaGetSymbolAddress((void**)&x3,  g_x3);
    float* x4;  cudaGetSymbolAddress((void**)&x4,  g_x4);
    float* fhp; cudaGetSymbolAddress((void**)&fhp, g_fh);
    float* wb2; cudaGetSymbolAddress((void**)&wb2, g_wb2);
    float* wb3; cudaGetSymbolAddress((void**)&wb3, g_wb3);
    float* wb4; cudaGetSymbolAddress((void**)&wb4, g_wb4);
    float* wb5; cudaGetSymbolAddress((void**)&wb5, g_wb5);

    cudaFuncSetAttribute((const void*)conv_gemm3<C1, C2, 2, H1, W1, H2, W2>,
                         cudaFuncAttributeMaxDynamicSharedMemorySize, SMEMB);
    cudaFuncSetAttribute((const void*)conv_gemm3<C2, C3, 2, H2, W2, H3, W3>,
                         cudaFuncAttributeMaxDynamicSharedMemorySize, SMEMB);
    cudaFuncSetAttribute((const void*)conv_gemm3<C3, C4, 2, H3, W3, HF, WF>,
                         cudaFuncAttributeMaxDynamicSharedMemorySize, SMEMB);
    cudaFuncSetAttribute((const void*)conv_gemm3<C4, C4, 1, HF, WF, HF, WF>,
                         cudaFuncAttributeMaxDynamicSharedMemorySize, SMEMB);

    wprep1<<<(36 * 32 + 255) / 256, 256>>>(w1);
    wprep_mma<<<(9  * 64  * 32 + 255) / 256, 256>>>(w2,  wb2, 32, 64, 9);
    wprep_mma<<<(18 * 128 * 32 + 255) / 256, 256>>>(w3,  wb3, 64, 128, 18);
    wprep_mma<<<(36 * 128 * 32 + 255) / 256, 256>>>(w4,  wb4, 128, 128, 36);
    wprep_mma<<<(36 * 128 * 32 + 255) / 256, 256>>>(fw1, wb5, 128, 128, 36);

    im2nhwc<<<(B_ * IMG_H * IMG_W + 255) / 256, 256>>>(images);
    zero_kernel<<<2048, 256>>>();

    conv1_kernel<<<B_ * H1 * W1 / 256, 256>>>(s1, b1);

    conv_gemm3<C1, C2, 2, H1, W1, H2, W2>
        <<<dim3(B_ * H2 * W2 / 128, 1), 256, SMEMB>>>(x1, wb2, s2, b2, x2);
    conv_gemm3<C2, C3, 2, H2, W2, H3, W3>
        <<<dim3(B_ * H3 * W3 / 128, 2), 256, SMEMB>>>(x2, wb3, s3, b3, x3);
    conv_gemm3<C3, C4, 2, H3, W3, HF, WF>
        <<<dim3(B_ * HF * WF / 128, 2), 256, SMEMB>>>(x3, wb4, s4, b4, x4);
    conv_gemm3<C4, C4, 1, HF, WF, HF, WF>
        <<<dim3(B_ * HF * WF / 128, 2), 256, SMEMB>>>(x4, wb5, fs1, fb1, fhp);

    heads_splat<<<B_ * HF * WF, 128>>>(x4, fhp, fw2, fb2, dw, db, ow, ob,
                                       camK, Tlc, imgh, imgw);

    finalize_kernel<<<B_ * SV / 32, 256>>>(out);
}

// round 15
// speedup vs baseline: 1.6721x; 1.6721x over previous
#include <cuda_runtime.h>
#include <cuda_bf16.h>
#include <math.h>
#include <stdint.h>

// ---------------- problem constants ----------------
#define B_    4
#define IMG_H 1024
#define IMG_W 1536

#define H1 512
#define W1 768
#define H2 256
#define W2 384
#define H3 128
#define W3 192
#define HF 64
#define WF 96

#define C1 32
#define C2 64
#define C3 128
#define C4 128

#define OUTC  64
#define DBINS 16
#define NYV 256
#define NXV 256
#define SV  (NYV*NXV)

// ---------------- scratch (static device globals; no allocation) ----------------
__device__ float g_im[(size_t)B_ * IMG_H * IMG_W * 4];   // NHWC padded C=4
__device__ float g_x1[(size_t)B_ * H1 * W1 * C1];
__device__ float g_x2[(size_t)B_ * H2 * W2 * C2];
__device__ float g_x3[(size_t)B_ * H3 * W3 * C3];
__device__ float g_x4[(size_t)B_ * HF * WF * C4];
__device__ float g_fh[(size_t)B_ * HF * WF * C4];
__device__ float g_canvas[(size_t)B_ * SV * OUTC];
__device__ float g_wacc[B_ * SV];

__device__ float g_wt1[36 * 32];
// conv2 weights: [k = tap*32+ic][OC] fp32 (R2 layout)
__device__ float g_wb2[288 * 64];
// conv3/4/5 weights: [chunk][oc][32] fp32
__device__ float g_wb3[18 * 128 * 32];
__device__ float g_wb4[36 * 128 * 32];
__device__ float g_wb5[36 * 128 * 32];

// ---------------- zero canvas ----------------
__global__ void zero_kernel() {
    int n1 = B_ * SV * OUTC;
    int n2 = B_ * SV;
    for (int i = blockIdx.x * blockDim.x + threadIdx.x; i < n1; i += gridDim.x * blockDim.x)
        g_canvas[i] = 0.f;
    for (int i = blockIdx.x * blockDim.x + threadIdx.x; i < n2; i += gridDim.x * blockDim.x)
        g_wacc[i] = 0.f;
}

// ---------------- conv1 weight transpose ----------------
__global__ void wprep1(const float* __restrict__ w) {
    int i = blockIdx.x * blockDim.x + threadIdx.x;
    if (i >= 36 * 32) return;
    int oc = i % 32;
    int k  = i / 32;
    int tap = k / 4;
    int ic  = k % 4;
    g_wt1[i] = (ic < 3) ? w[(oc * 3 + ic) * 9 + tap] : 0.f;
}

// ---------------- conv2 weight prep: [tap*CPAD+ic][OC] (R2 layout) ----------------
__global__ void wprepKO(const float* __restrict__ w, float* __restrict__ o,
                        int CIN, int CPAD, int OC, int total)
{
    int i = blockIdx.x * blockDim.x + threadIdx.x;
    if (i >= total) return;
    int oc = i % OC;
    int k  = i / OC;
    int tap = k / CPAD;
    int ic  = k % CPAD;
    o[i] = (ic < CIN) ? w[(oc * CIN + ic) * 9 + tap] : 0.f;
}

// ---------------- wide-layer weight prep: [chunk][oc][32] fp32 ----------------
__global__ void wprep_mma(const float* __restrict__ w, float* __restrict__ out,
                          int CIN, int OC, int NCH) {
    int i = blockIdx.x * blockDim.x + threadIdx.x;
    if (i >= NCH * OC * 32) return;
    int j  = i & 31;
    int oc = (i >> 5) % OC;
    int ch = i / (OC * 32);
    int kg = ch * 32 + j;
    int tap = kg / CIN;
    int ic  = kg % CIN;
    out[i] = w[(oc * CIN + ic) * 9 + tap];
}

// ---------------- images NCHW -> NHWC padded C=4 ----------------
__global__ void im2nhwc(const float* __restrict__ im) {
    int i = blockIdx.x * blockDim.x + threadIdx.x;
    const int HW = IMG_H * IMG_W;
    if (i >= B_ * HW) return;
    int b = i / HW;
    int p = i % HW;
    const float* base = im + (size_t)b * 3 * HW + p;
    float4 v;
    v.x = base[0];
    v.y = base[HW];
    v.z = base[2 * HW];
    v.w = 0.f;
    *(float4*)&g_im[(size_t)i * 4] = v;
}

// ---------------- conv1: direct fp32 ----------------
__global__ __launch_bounds__(256) void conv1_kernel(const float* __restrict__ sc,
                                                    const float* __restrict__ bi) {
    __shared__ float ws[36 * 32];
    __shared__ float ssc[32], sbi[32];
    int tid = threadIdx.x;
    for (int i = tid; i < 36 * 32; i += 256) ws[i] = g_wt1[i];
    if (tid < 32) { ssc[tid] = sc[tid]; sbi[tid] = bi[tid]; }
    __syncthreads();

    int p = blockIdx.x * 256 + tid;
    const int HW = H1 * W1;
    int b  = p / HW;
    int r  = p % HW;
    int oh = r / W1;
    int ow = r % W1;
    int ihb = oh * 2 - 1;
    int iwb = ow * 2 - 1;

    float4 patch[9];
    #pragma unroll
    for (int t = 0; t < 9; t++) {
        int kh = t / 3, kw = t % 3;
        int ih = ihb + kh, iw = iwb + kw;
        float4 v = make_float4(0.f, 0.f, 0.f, 0.f);
        if ((unsigned)ih < (unsigned)IMG_H && (unsigned)iw < (unsigned)IMG_W)
            v = *(const float4*)&g_im[(((size_t)b * IMG_H + ih) * IMG_W + iw) * 4];
        patch[t] = v;
    }

    float4 acc[8];
    #pragma unroll
    for (int q = 0; q < 8; q++) acc[q] = make_float4(0.f, 0.f, 0.f, 0.f);

    #pragma unroll
    for (int t = 0; t < 9; t++) {
        #pragma unroll
        for (int ic = 0; ic < 4; ic++) {
            float a = (ic == 0) ? patch[t].x : (ic == 1) ? patch[t].y :
                      (ic == 2) ? patch[t].z : patch[t].w;
            int k = t * 4 + ic;
            #pragma unroll
            for (int q = 0; q < 8; q++) {
                float4 wv = ((float4*)ws)[k * 8 + q];
                acc[q].x += a * wv.x;
                acc[q].y += a * wv.y;
                acc[q].z += a * wv.z;
                acc[q].w += a * wv.w;
            }
        }
    }

    float* outp = &g_x1[(size_t)p * C1];
    #pragma unroll
    for (int q = 0; q < 8; q++) {
        float4 v;
        v.x = fmaxf(acc[q].x * ssc[q * 4 + 0] + sbi[q * 4 + 0], 0.f);
        v.y = fmaxf(acc[q].y * ssc[q * 4 + 1] + sbi[q * 4 + 1], 0.f);
        v.z = fmaxf(acc[q].z * ssc[q * 4 + 2] + sbi[q * 4 + 2], 0.f);
        v.w = fmaxf(acc[q].w * ssc[q * 4 + 3] + sbi[q * 4 + 3], 0.f);
        *(float4*)&outp[q * 4] = v;
    }
}

// ---------------- R2 implicit-GEMM conv (BN=64) — used for conv2 ----------------
template <int CIN, int OC, int S, int H, int W, int OH, int OW>
__global__ __launch_bounds__(256) void conv_gemm(const float* __restrict__ in,
                                                 const float* __restrict__ wt,
                                                 const float* __restrict__ sc,
                                                 const float* __restrict__ bi,
                                                 float* __restrict__ out)
{
    constexpr int NCH = CIN / 32;
    constexpr int ITERS = 9 * NCH;

    __shared__ float As[128 * 33];
    __shared__ float Bs[32 * 64];

    const int tid  = threadIdx.x;
    const int pix0 = blockIdx.x * 128;
    const int oc0  = blockIdx.y * 64;

    const int lp  = tid >> 3;
    const int seg = tid & 7;
    int ihb[4], iwb[4], basei[4];
    #pragma unroll
    for (int i = 0; i < 4; i++) {
        int p = pix0 + lp + 32 * i;
        int b = p / (OH * OW);
        int r = p % (OH * OW);
        int oh = r / OW;
        int ow = r % OW;
        ihb[i] = oh * S - 1;
        iwb[i] = ow * S - 1;
        basei[i] = ((b * H + ihb[i]) * W + iwb[i]) * CIN;
    }

    const int krow  = tid >> 4;
    const int ocseg = tid & 15;

    const int pg = tid >> 4;
    const int og = tid & 15;

    float4 acc[8];
    #pragma unroll
    for (int r = 0; r < 8; r++) acc[r] = make_float4(0.f, 0.f, 0.f, 0.f);

    float4 aR[4];
    float4 bR[2];

    auto loadg = [&](int it) {
        int tap   = it / NCH;
        int chunk = it % NCH;
        int kh = tap / 3, kw = tap % 3;
        #pragma unroll
        for (int i = 0; i < 4; i++) {
            float4 v = make_float4(0.f, 0.f, 0.f, 0.f);
            if ((unsigned)(ihb[i] + kh) < (unsigned)H &&
                (unsigned)(iwb[i] + kw) < (unsigned)W)
                v = *(const float4*)&in[basei[i] + (kh * W + kw) * CIN + chunk * 32 + seg * 4];
            aR[i] = v;
        }
        bR[0] = *(const float4*)&wt[(it * 32 + krow)      * OC + oc0 + ocseg * 4];
        bR[1] = *(const float4*)&wt[(it * 32 + krow + 16) * OC + oc0 + ocseg * 4];
    };

    loadg(0);
    for (int it = 0; it < ITERS; it++) {
        __syncthreads();
        #pragma unroll
        for (int i = 0; i < 4; i++) {
            int row = lp + 32 * i;
            As[row * 33 + seg * 4 + 0] = aR[i].x;
            As[row * 33 + seg * 4 + 1] = aR[i].y;
            As[row * 33 + seg * 4 + 2] = aR[i].z;
            As[row * 33 + seg * 4 + 3] = aR[i].w;
        }
        ((float4*)Bs)[krow * 16 + ocseg]        = bR[0];
        ((float4*)Bs)[(krow + 16) * 16 + ocseg] = bR[1];
        __syncthreads();
        if (it + 1 < ITERS) loadg(it + 1);

        #pragma unroll
        for (int k = 0; k < 32; k++) {
            float4 b4 = ((float4*)Bs)[k * 16 + og];
            #pragma unroll
            for (int r = 0; r < 8; r++) {
                float a = As[(pg * 8 + r) * 33 + k];
                acc[r].x += a * b4.x;
                acc[r].y += a * b4.y;
                acc[r].z += a * b4.z;
                acc[r].w += a * b4.w;
            }
        }
    }

    float4 s4 = *(const float4*)&sc[oc0 + og * 4];
    float4 b4 = *(const float4*)&bi[oc0 + og * 4];
    #pragma unroll
    for (int r = 0; r < 8; r++) {
        int p = pix0 + pg * 8 + r;
        float4 v;
        v.x = fmaxf(acc[r].x * s4.x + b4.x, 0.f);
        v.y = fmaxf(acc[r].y * s4.y + b4.y, 0.f);
        v.z = fmaxf(acc[r].z * s4.z + b4.z, 0.f);
        v.w = fmaxf(acc[r].w * s4.w + b4.w, 0.f);
        *(float4*)&out[(size_t)p * OC + oc0 + og * 4] = v;
    }
}

// ---------------- wide implicit-GEMM conv (BN=OC=128, 8x8 thread tile) ----------------
// BM=128 pix, BN=128 oc, BK=32. 256 threads. A tile loaded ONCE per pixel block.
template <int CIN, int S, int H, int W, int OH, int OW>
__global__ __launch_bounds__(256)
void conv_gemmW(const float* __restrict__ in, const float* __restrict__ wb,
                const float* __restrict__ sc, const float* __restrict__ bi,
                float* __restrict__ out)
{
    constexpr int OC  = 128;
    constexpr int CPT = CIN / 32;     // chunks per tap
    constexpr int ITERS = 9 * CPT;

    __shared__ float As[128 * 33];
    __shared__ float Bs[32 * 132];

    const int tid  = threadIdx.x;
    const int pix0 = blockIdx.x * 128;

    // A mapping (R2): lp = tid>>3 loads 4 pixels, seg = tid&7 -> 4 channels
    const int lp  = tid >> 3;
    const int seg = tid & 7;
    int ihb[4], iwb[4], basei[4];
    #pragma unroll
    for (int i = 0; i < 4; i++) {
        int p = pix0 + lp + 32 * i;
        int b = p / (OH * OW);
        int r = p % (OH * OW);
        int oh = r / OW;
        int ow = r % OW;
        ihb[i] = oh * S - 1;
        iwb[i] = ow * S - 1;
        basei[i] = ((b * H + ihb[i]) * W + iwb[i]) * CIN;
    }

    // B mapping: bo = oc row (0..127), kq = k-half offset {0,16}
    const int bo = tid & 127;
    const int kq = (tid >> 7) * 16;

    // compute mapping: pg = pixel group (8), og = oc group (8)
    const int pg = tid >> 4;
    const int og = tid & 15;

    float4 acc[8][2];
    #pragma unroll
    for (int r = 0; r < 8; r++) {
        acc[r][0] = make_float4(0.f, 0.f, 0.f, 0.f);
        acc[r][1] = make_float4(0.f, 0.f, 0.f, 0.f);
    }

    float4 aR[4];
    float4 bR[4];

    auto loadg = [&](int it) {
        int tap   = it / CPT;
        int chunk = it % CPT;
        int kh = tap / 3, kw = tap % 3;
        #pragma unroll
        for (int i = 0; i < 4; i++) {
            float4 v = make_float4(0.f, 0.f, 0.f, 0.f);
            if ((unsigned)(ihb[i] + kh) < (unsigned)H &&
                (unsigned)(iwb[i] + kw) < (unsigned)W)
                v = *(const float4*)&in[basei[i] + (kh * W + kw) * CIN + chunk * 32 + seg * 4];
            aR[i] = v;
        }
        const float4* bsrc = (const float4*)&wb[((size_t)it * OC + bo) * 32 + kq];
        bR[0] = bsrc[0];
        bR[1] = bsrc[1];
        bR[2] = bsrc[2];
        bR[3] = bsrc[3];
    };

    loadg(0);
    for (int it = 0; it < ITERS; it++) {
        __syncthreads();
        #pragma unroll
        for (int i = 0; i < 4; i++) {
            int row = lp + 32 * i;
            As[row * 33 + seg * 4 + 0] = aR[i].x;
            As[row * 33 + seg * 4 + 1] = aR[i].y;
            As[row * 33 + seg * 4 + 2] = aR[i].z;
            As[row * 33 + seg * 4 + 3] = aR[i].w;
        }
        {
            const float* bf = (const float*)bR;
            #pragma unroll
            for (int j = 0; j < 16; j++)
                Bs[(kq + j) * 132 + bo] = bf[j];
        }
        __syncthreads();
        if (it + 1 < ITERS) loadg(it + 1);

        #pragma unroll
        for (int k = 0; k < 32; k++) {
            float4 b0 = *(const float4*)&Bs[k * 132 + og * 8];
            float4 b1 = *(const float4*)&Bs[k * 132 + og * 8 + 4];
            #pragma unroll
            for (int r = 0; r < 8; r++) {
                float a = As[(pg * 8 + r) * 33 + k];
                acc[r][0].x += a * b0.x;
                acc[r][0].y += a * b0.y;
                acc[r][0].z += a * b0.z;
                acc[r][0].w += a * b0.w;
                acc[r][1].x += a * b1.x;
                acc[r][1].y += a * b1.y;
                acc[r][1].z += a * b1.z;
                acc[r][1].w += a * b1.w;
            }
        }
    }

    float4 s0 = *(const float4*)&sc[og * 8];
    float4 s1 = *(const float4*)&sc[og * 8 + 4];
    float4 c0 = *(const float4*)&bi[og * 8];
    float4 c1 = *(const float4*)&bi[og * 8 + 4];
    #pragma unroll
    for (int r = 0; r < 8; r++) {
        int p = pix0 + pg * 8 + r;
        float4 v0, v1;
        v0.x = fmaxf(acc[r][0].x * s0.x + c0.x, 0.f);
        v0.y = fmaxf(acc[r][0].y * s0.y + c0.y, 0.f);
        v0.z = fmaxf(acc[r][0].z * s0.z + c0.z, 0.f);
        v0.w = fmaxf(acc[r][0].w * s0.w + c0.w, 0.f);
        v1.x = fmaxf(acc[r][1].x * s1.x + c1.x, 0.f);
        v1.y = fmaxf(acc[r][1].y * s1.y + c1.y, 0.f);
        v1.z = fmaxf(acc[r][1].z * s1.z + c1.z, 0.f);
        v1.w = fmaxf(acc[r][1].w * s1.w + c1.w, 0.f);
        float4* dst = (float4*)&out[(size_t)p * OC + og * 8];
        dst[0] = v0;
        dst[1] = v1;
    }
}

// ---------------- heads + depth lift + backprojection + gaussian splat ----------------
__global__ void heads_splat(const float* __restrict__ x4, const float* __restrict__ fh,
                            const float* __restrict__ fw2, const float* __restrict__ fb2,
                            const float* __restrict__ dw,  const float* __restrict__ db,
                            const float* __restrict__ oww, const float* __restrict__ ob,
                            const float* __restrict__ camK, const float* __restrict__ Tlc,
                            const int* __restrict__ imgh, const int* __restrict__ imgw)
{
    const int pix = blockIdx.x;
    const int w   = pix % WF;
    int t = pix / WF;
    const int h = t % HF;
    const int b = t / HF;
    const int tid = threadIdx.x;

    __shared__ float sx4[C4];
    __shared__ float sfh[C4];
    __shared__ float sfeat[OUTC];
    __shared__ float sdl[DBINS];
    __shared__ float sprm[4];

    sx4[tid] = x4[(size_t)pix * C4 + tid];
    sfh[tid] = fh[(size_t)pix * C4 + tid];
    __syncthreads();

    if (tid < OUTC) {
        float a = 0.f;
        const float* wr = fw2 + tid * C4;
        #pragma unroll 8
        for (int k = 0; k < C4; k++) a += wr[k] * sfh[k];
        sfeat[tid] = a + fb2[tid];
    } else if (tid < OUTC + DBINS) {
        int d = tid - OUTC;
        float a = 0.f;
        const float* wr = dw + d * C4;
        #pragma unroll 8
        for (int k = 0; k < C4; k++) a += wr[k] * sx4[k];
        sdl[d] = a + db[d];
    } else if (tid == OUTC + DBINS) {
        float a = 0.f;
        #pragma unroll 8
        for (int k = 0; k < C4; k++) a += oww[k] * sx4[k];
        sprm[0] = 1.f / (1.f + expf(-(a + ob[0])));
    }
    __syncthreads();

    if (tid == 0) {
        float m = -1e30f;
        #pragma unroll
        for (int d = 0; d < DBINS; d++) m = fmaxf(m, sdl[d]);
        float sum = 0.f, zz = 0.f;
        #pragma unroll
        for (int d = 0; d < DBINS; d++) {
            float e = expf(sdl[d] - m);
            sum += e;
            zz  += e * (1.f + (float)d * (59.f / 15.f));
        }
        float z = zz / sum;

        float ihf = (float)imgh[0];
        float iwf = (float)imgw[0];
        float ys = ((float)h + 0.5f) * (ihf / (float)HF);
        float xs = ((float)w + 0.5f) * (iwf / (float)WF);

        const float* K = camK + b * 9;
        float fx = fmaxf(K[0], 1e-6f), fy = fmaxf(K[4], 1e-6f);
        float cx = K[2], cy = K[5];
        float xc = (xs - cx) * z / fx;
        float yc = (ys - cy) * z / fy;

        const float* T = Tlc + b * 16;
        float lx = T[0] * xc + T[1] * yc + T[2]  * z + T[3];
        float ly = T[4] * xc + T[5] * yc + T[6]  * z + T[7];
        float lz = T[8] * xc + T[9] * yc + T[10] * z + T[11];

        int xi = (int)floorf((lx + 51.2f) * 2.5f);
        int yi = (int)floorf((ly + 51.2f) * 2.5f);
        bool inb = (xi >= 0) && (xi < NXV) && (yi >= 0) && (yi < NYV) &&
                   (lz >= -5.f) && (lz < 3.f);
        float op = sprm[0];
        float bw = (op >= 0.05f && inb) ? op : 0.f;
        sprm[1] = bw;
        sprm[2] = __int_as_float(xi);
        sprm[3] = __int_as_float(yi);
    }
    __syncthreads();

    float bw = sprm[1];
    if (bw <= 0.f) return;
    int xi = __float_as_int(sprm[2]);
    int yi = __float_as_int(sprm[3]);

    #pragma unroll
    for (int tap = 0; tap < 9; tap++) {
        int dy = tap / 3 - 1;
        int dx = tap % 3 - 1;
        int ty = yi + dy;
        int tx = xi + dx;
        if ((unsigned)tx >= (unsigned)NXV || (unsigned)ty >= (unsigned)NYV) continue;
        float kwv = expf(-(float)(dx * dx + dy * dy) * (1.f / 1.28f));
        float sw = bw * kwv;
        int vox = b * SV + ty * NXV + tx;
        if (tid < OUTC) atomicAdd(&g_canvas[(size_t)vox * OUTC + tid], sfeat[tid] * sw);
        if (tid == OUTC) atomicAdd(&g_wacc[vox], sw);
    }
}

// ---------------- normalize + transpose (pix, C) -> (B, C, NY, NX) ----------------
__global__ void finalize_kernel(float* __restrict__ out)
{
    __shared__ float tile[OUTC][33];
    int gp  = blockIdx.x * 32;
    int tid = threadIdx.x;

    for (int i = tid; i < 32 * OUTC; i += 256) {
        int p = i >> 6;
        int c = i & 63;
        float wv  = g_wacc[gp + p];
        float inv = (wv > 0.f) ? (1.f / fmaxf(wv, 1e-6f)) : 0.f;
        tile[c][p] = g_canvas[(size_t)(gp + p) * OUTC + c] * inv;
    }
    __syncthreads();

    int b  = gp >> 16;
    int p0 = gp & 65535;
    for (int i = tid; i < OUTC * 32; i += 256) {
        int c = i >> 5;
        int x = i & 31;
        out[(((b * OUTC) + c) << 16) + p0 + x] = tile[c][x];
    }
}

// ---------------- launch ----------------
extern "C" void kernel_launch(void* const* d_in, const int* in_sizes, int n_in,
                              void* d_out, int out_size)
{
    const float* images = (const float*)d_in[0];
    const float* camK   = (const float*)d_in[1];
    const float* Tlc    = (const float*)d_in[2];
    const float* w1 = (const float*)d_in[3];
    const float* s1 = (const float*)d_in[4];
    const float* b1 = (const float*)d_in[5];
    const float* w2 = (const float*)d_in[6];
    const float* s2 = (const float*)d_in[7];
    const float* b2 = (const float*)d_in[8];
    const float* w3 = (const float*)d_in[9];
    const float* s3 = (const float*)d_in[10];
    const float* b3 = (const float*)d_in[11];
    const float* w4 = (const float*)d_in[12];
    const float* s4 = (const float*)d_in[13];
    const float* b4 = (const float*)d_in[14];
    const float* fw1 = (const float*)d_in[15];
    const float* fs1 = (const float*)d_in[16];
    const float* fb1 = (const float*)d_in[17];
    const float* fw2 = (const float*)d_in[18];
    const float* fb2 = (const float*)d_in[19];
    const float* dw  = (const float*)d_in[20];
    const float* db  = (const float*)d_in[21];
    const float* ow  = (const float*)d_in[22];
    const float* ob  = (const float*)d_in[23];
    const int* imgh  = (const int*)d_in[24];
    const int* imgw  = (const int*)d_in[25];
    float* out = (float*)d_out;

    float* x1;  cudaGetSymbolAddress((void**)&x1,  g_x1);
    float* x2;  cudaGetSymbolAddress((void**)&x2,  g_x2);
    float* x3;  cudaGetSymbolAddress((void**)&x3,  g_x3);
    float* x4;  cudaGetSymbolAddress((void**)&x4,  g_x4);
    float* fhp; cudaGetSymbolAddress((void**)&fhp, g_fh);
    float* wb2; cudaGetSymbolAddress((void**)&wb2, g_wb2);
    float* wb3; cudaGetSymbolAddress((void**)&wb3, g_wb3);
    float* wb4; cudaGetSymbolAddress((void**)&wb4, g_wb4);
    float* wb5; cudaGetSymbolAddress((void**)&wb5, g_wb5);

    wprep1<<<(36 * 32 + 255) / 256, 256>>>(w1);
    wprepKO<<<(288 * 64 + 255) / 256, 256>>>(w2, wb2, 32, 32, 64, 288 * 64);
    wprep_mma<<<(18 * 128 * 32 + 255) / 256, 256>>>(w3,  wb3, 64, 128, 18);
    wprep_mma<<<(36 * 128 * 32 + 255) / 256, 256>>>(w4,  wb4, 128, 128, 36);
    wprep_mma<<<(36 * 128 * 32 + 255) / 256, 256>>>(fw1, wb5, 128, 128, 36);

    im2nhwc<<<(B_ * IMG_H * IMG_W + 255) / 256, 256>>>(images);
    zero_kernel<<<2048, 256>>>();

    conv1_kernel<<<B_ * H1 * W1 / 256, 256>>>(s1, b1);

    conv_gemm<C1, C2, 2, H1, W1, H2, W2>
        <<<dim3(B_ * H2 * W2 / 128, 1), 256>>>(x1, wb2, s2, b2, x2);

    conv_gemmW<C2, 2, H2, W2, H3, W3>
        <<<B_ * H3 * W3 / 128, 256>>>(x2, wb3, s3, b3, x3);
    conv_gemmW<C3, 2, H3, W3, HF, WF>
        <<<B_ * HF * WF / 128, 256>>>(x3, wb4, s4, b4, x4);
    conv_gemmW<C4, 1, HF, WF, HF, WF>
        <<<B_ * HF * WF / 128, 256>>>(x4, wb5, fs1, fb1, fhp);

    heads_splat<<<B_ * HF * WF, 128>>>(x4, fhp, fw2, fb2, dw, db, ow, ob,
                                       camK, Tlc, imgh, imgw);

    finalize_kernel<<<B_ * SV / 32, 256>>>(out);
}

// round 16
// speedup vs baseline: 1.8326x; 1.0960x over previous
#include <cuda_runtime.h>
#include <cuda_bf16.h>
#include <math.h>
#include <stdint.h>

// ---------------- problem constants ----------------
#define B_    4
#define IMG_H 1024
#define IMG_W 1536

#define H1 512
#define W1 768
#define H2 256
#define W2 384
#define H3 128
#define W3 192
#define HF 64
#define WF 96

#define C1 32
#define C2 64
#define C3 128
#define C4 128

#define OUTC  64
#define DBINS 16
#define NYV 256
#define NXV 256
#define SV  (NYV*NXV)

// ---------------- scratch (static device globals; no allocation) ----------------
__device__ float g_im[(size_t)B_ * IMG_H * IMG_W * 4];   // NHWC padded C=4
__device__ float g_x1[(size_t)B_ * H1 * W1 * C1];
__device__ float g_x2[(size_t)B_ * H2 * W2 * C2];
__device__ float g_x3[(size_t)B_ * H3 * W3 * C3];
__device__ float g_x4[(size_t)B_ * HF * WF * C4];
__device__ float g_fh[(size_t)B_ * HF * WF * C4];
__device__ float g_canvas[(size_t)B_ * SV * OUTC];
__device__ float g_wacc[B_ * SV];

__device__ float g_wt1[36 * 32];
// weights [k = tap*CPAD+ic][OC] fp32 (R2 layout)
__device__ float g_wb2[288 * 64];
__device__ float g_wb3[576 * 128];
__device__ float g_wb4[1152 * 128];
__device__ float g_wb5[1152 * 128];

// ---------------- zero canvas ----------------
__global__ void zero_kernel() {
    int n1 = B_ * SV * OUTC;
    int n2 = B_ * SV;
    for (int i = blockIdx.x * blockDim.x + threadIdx.x; i < n1; i += gridDim.x * blockDim.x)
        g_canvas[i] = 0.f;
    for (int i = blockIdx.x * blockDim.x + threadIdx.x; i < n2; i += gridDim.x * blockDim.x)
        g_wacc[i] = 0.f;
}

// ---------------- conv1 weight transpose ----------------
__global__ void wprep1(const float* __restrict__ w) {
    int i = blockIdx.x * blockDim.x + threadIdx.x;
    if (i >= 36 * 32) return;
    int oc = i % 32;
    int k  = i / 32;
    int tap = k / 4;
    int ic  = k % 4;
    g_wt1[i] = (ic < 3) ? w[(oc * 3 + ic) * 9 + tap] : 0.f;
}

// ---------------- weight prep: OIHW -> [tap*CPAD+ic][OC] ----------------
__global__ void wprepKO(const float* __restrict__ w, float* __restrict__ o,
                        int CIN, int CPAD, int OC, int total)
{
    int i = blockIdx.x * blockDim.x + threadIdx.x;
    if (i >= total) return;
    int oc = i % OC;
    int k  = i / OC;
    int tap = k / CPAD;
    int ic  = k % CPAD;
    o[i] = (ic < CIN) ? w[(oc * CIN + ic) * 9 + tap] : 0.f;
}

// ---------------- images NCHW -> NHWC padded C=4 ----------------
__global__ void im2nhwc(const float* __restrict__ im) {
    int i = blockIdx.x * blockDim.x + threadIdx.x;
    const int HW = IMG_H * IMG_W;
    if (i >= B_ * HW) return;
    int b = i / HW;
    int p = i % HW;
    const float* base = im + (size_t)b * 3 * HW + p;
    float4 v;
    v.x = base[0];
    v.y = base[HW];
    v.z = base[2 * HW];
    v.w = 0.f;
    *(float4*)&g_im[(size_t)i * 4] = v;
}

// ---------------- conv1: direct fp32 ----------------
__global__ __launch_bounds__(256) void conv1_kernel(const float* __restrict__ sc,
                                                    const float* __restrict__ bi) {
    __shared__ float ws[36 * 32];
    __shared__ float ssc[32], sbi[32];
    int tid = threadIdx.x;
    for (int i = tid; i < 36 * 32; i += 256) ws[i] = g_wt1[i];
    if (tid < 32) { ssc[tid] = sc[tid]; sbi[tid] = bi[tid]; }
    __syncthreads();

    int p = blockIdx.x * 256 + tid;
    const int HW = H1 * W1;
    int b  = p / HW;
    int r  = p % HW;
    int oh = r / W1;
    int ow = r % W1;
    int ihb = oh * 2 - 1;
    int iwb = ow * 2 - 1;

    float4 patch[9];
    #pragma unroll
    for (int t = 0; t < 9; t++) {
        int kh = t / 3, kw = t % 3;
        int ih = ihb + kh, iw = iwb + kw;
        float4 v = make_float4(0.f, 0.f, 0.f, 0.f);
        if ((unsigned)ih < (unsigned)IMG_H && (unsigned)iw < (unsigned)IMG_W)
            v = *(const float4*)&g_im[(((size_t)b * IMG_H + ih) * IMG_W + iw) * 4];
        patch[t] = v;
    }

    float4 acc[8];
    #pragma unroll
    for (int q = 0; q < 8; q++) acc[q] = make_float4(0.f, 0.f, 0.f, 0.f);

    #pragma unroll
    for (int t = 0; t < 9; t++) {
        #pragma unroll
        for (int ic = 0; ic < 4; ic++) {
            float a = (ic == 0) ? patch[t].x : (ic == 1) ? patch[t].y :
                      (ic == 2) ? patch[t].z : patch[t].w;
            int k = t * 4 + ic;
            #pragma unroll
            for (int q = 0; q < 8; q++) {
                float4 wv = ((float4*)ws)[k * 8 + q];
                acc[q].x += a * wv.x;
                acc[q].y += a * wv.y;
                acc[q].z += a * wv.z;
                acc[q].w += a * wv.w;
            }
        }
    }

    float* outp = &g_x1[(size_t)p * C1];
    #pragma unroll
    for (int q = 0; q < 8; q++) {
        float4 v;
        v.x = fmaxf(acc[q].x * ssc[q * 4 + 0] + sbi[q * 4 + 0], 0.f);
        v.y = fmaxf(acc[q].y * ssc[q * 4 + 1] + sbi[q * 4 + 1], 0.f);
        v.z = fmaxf(acc[q].z * ssc[q * 4 + 2] + sbi[q * 4 + 2], 0.f);
        v.w = fmaxf(acc[q].w * ssc[q * 4 + 3] + sbi[q * 4 + 3], 0.f);
        *(float4*)&outp[q * 4] = v;
    }
}

// ---------------- R2 implicit-GEMM conv, double-buffered (ONE sync per k-chunk) ----------
// BM=128 pix, BN=64 oc, BK=32. 256 threads, thread tile 8 pix x 4 oc. R2 mappings verbatim.
#define A_CHF (128 * 33)          // floats per A buffer
#define B_CHF (32 * 64)           // floats per B buffer
#define SMEMDB ((2 * A_CHF + 2 * B_CHF) * 4)   // 50176 bytes

template <int CIN, int OC, int S, int H, int W, int OH, int OW>
__global__ __launch_bounds__(256)
void conv_gemm_db(const float* __restrict__ in, const float* __restrict__ wt,
                  const float* __restrict__ sc, const float* __restrict__ bi,
                  float* __restrict__ out)
{
    constexpr int NCH = CIN / 32;
    constexpr int ITERS = 9 * NCH;

    extern __shared__ float smf[];
    float* As = smf;                  // [2][128*33]
    float* Bs = smf + 2 * A_CHF;      // [2][32*64]

    const int tid  = threadIdx.x;
    const int pix0 = blockIdx.x * 128;
    const int oc0  = blockIdx.y * 64;

    // A-load mapping: 32 load-pixels x 8 segments of 4 k
    const int lp  = tid >> 3;
    const int seg = tid & 7;
    int ihb[4], iwb[4], basei[4];
    #pragma unroll
    for (int i = 0; i < 4; i++) {
        int p = pix0 + lp + 32 * i;
        int b = p / (OH * OW);
        int r = p % (OH * OW);
        int oh = r / OW;
        int ow = r % OW;
        ihb[i] = oh * S - 1;
        iwb[i] = ow * S - 1;
        basei[i] = ((b * H + ihb[i]) * W + iwb[i]) * CIN;
    }

    // B-load mapping
    const int krow  = tid >> 4;
    const int ocseg = tid & 15;

    // compute mapping: 16 pixel-groups x 16 oc-groups
    const int pg = tid >> 4;
    const int og = tid & 15;

    float4 acc[8];
    #pragma unroll
    for (int r = 0; r < 8; r++) acc[r] = make_float4(0.f, 0.f, 0.f, 0.f);

    float4 aR[4];
    float4 bR[2];

    auto loadg = [&](int it) {
        int tap   = it / NCH;
        int chunk = it % NCH;
        int kh = tap / 3, kw = tap % 3;
        #pragma unroll
        for (int i = 0; i < 4; i++) {
            float4 v = make_float4(0.f, 0.f, 0.f, 0.f);
            if ((unsigned)(ihb[i] + kh) < (unsigned)H &&
                (unsigned)(iwb[i] + kw) < (unsigned)W)
                v = *(const float4*)&in[basei[i] + (kh * W + kw) * CIN + chunk * 32 + seg * 4];
            aR[i] = v;
        }
        bR[0] = *(const float4*)&wt[(it * 32 + krow)      * OC + oc0 + ocseg * 4];
        bR[1] = *(const float4*)&wt[(it * 32 + krow + 16) * OC + oc0 + ocseg * 4];
    };

    auto store_s = [&](int buf) {
        float* Ab = As + buf * A_CHF;
        #pragma unroll
        for (int i = 0; i < 4; i++) {
            int row = lp + 32 * i;
            Ab[row * 33 + seg * 4 + 0] = aR[i].x;
            Ab[row * 33 + seg * 4 + 1] = aR[i].y;
            Ab[row * 33 + seg * 4 + 2] = aR[i].z;
            Ab[row * 33 + seg * 4 + 3] = aR[i].w;
        }
        float4* Bb = (float4*)(Bs + buf * B_CHF);
        Bb[krow * 16 + ocseg]        = bR[0];
        Bb[(krow + 16) * 16 + ocseg] = bR[1];
    };

    loadg(0);
    store_s(0);
    __syncthreads();

    for (int it = 0; it < ITERS; it++) {
        const int buf = it & 1;
        if (it + 1 < ITERS) loadg(it + 1);

        const float* Ab = As + buf * A_CHF;
        const float4* Bb = (const float4*)(Bs + buf * B_CHF);

        #pragma unroll
        for (int k = 0; k < 32; k++) {
            float4 b4 = Bb[k * 16 + og];
            #pragma unroll
            for (int r = 0; r < 8; r++) {
                float a = Ab[(pg * 8 + r) * 33 + k];
                acc[r].x += a * b4.x;
                acc[r].y += a * b4.y;
                acc[r].z += a * b4.z;
                acc[r].w += a * b4.w;
            }
        }

        if (it + 1 < ITERS) {
            store_s((it + 1) & 1);
            __syncthreads();
        }
    }

    float4 s4 = *(const float4*)&sc[oc0 + og * 4];
    float4 b4 = *(const float4*)&bi[oc0 + og * 4];
    #pragma unroll
    for (int r = 0; r < 8; r++) {
        int p = pix0 + pg * 8 + r;
        float4 v;
        v.x = fmaxf(acc[r].x * s4.x + b4.x, 0.f);
        v.y = fmaxf(acc[r].y * s4.y + b4.y, 0.f);
        v.z = fmaxf(acc[r].z * s4.z + b4.z, 0.f);
        v.w = fmaxf(acc[r].w * s4.w + b4.w, 0.f);
        *(float4*)&out[(size_t)p * OC + oc0 + og * 4] = v;
    }
}

// ---------------- heads + depth lift + backprojection + gaussian splat ----------------
__global__ void heads_splat(const float* __restrict__ x4, const float* __restrict__ fh,
                            const float* __restrict__ fw2, const float* __restrict__ fb2,
                            const float* __restrict__ dw,  const float* __restrict__ db,
                            const float* __restrict__ oww, const float* __restrict__ ob,
                            const float* __restrict__ camK, const float* __restrict__ Tlc,
                            const int* __restrict__ imgh, const int* __restrict__ imgw)
{
    const int pix = blockIdx.x;
    const int w   = pix % WF;
    int t = pix / WF;
    const int h = t % HF;
    const int b = t / HF;
    const int tid = threadIdx.x;

    __shared__ float sx4[C4];
    __shared__ float sfh[C4];
    __shared__ float sfeat[OUTC];
    __shared__ float sdl[DBINS];
    __shared__ float sprm[4];

    sx4[tid] = x4[(size_t)pix * C4 + tid];
    sfh[tid] = fh[(size_t)pix * C4 + tid];
    __syncthreads();

    if (tid < OUTC) {
        float a = 0.f;
        const float* wr = fw2 + tid * C4;
        #pragma unroll 8
        for (int k = 0; k < C4; k++) a += wr[k] * sfh[k];
        sfeat[tid] = a + fb2[tid];
    } else if (tid < OUTC + DBINS) {
        int d = tid - OUTC;
        float a = 0.f;
        const float* wr = dw + d * C4;
        #pragma unroll 8
        for (int k = 0; k < C4; k++) a += wr[k] * sx4[k];
        sdl[d] = a + db[d];
    } else if (tid == OUTC + DBINS) {
        float a = 0.f;
        #pragma unroll 8
        for (int k = 0; k < C4; k++) a += oww[k] * sx4[k];
        sprm[0] = 1.f / (1.f + expf(-(a + ob[0])));
    }
    __syncthreads();

    if (tid == 0) {
        float m = -1e30f;
        #pragma unroll
        for (int d = 0; d < DBINS; d++) m = fmaxf(m, sdl[d]);
        float sum = 0.f, zz = 0.f;
        #pragma unroll
        for (int d = 0; d < DBINS; d++) {
            float e = expf(sdl[d] - m);
            sum += e;
            zz  += e * (1.f + (float)d * (59.f / 15.f));
        }
        float z = zz / sum;

        float ihf = (float)imgh[0];
        float iwf = (float)imgw[0];
        float ys = ((float)h + 0.5f) * (ihf / (float)HF);
        float xs = ((float)w + 0.5f) * (iwf / (float)WF);

        const float* K = camK + b * 9;
        float fx = fmaxf(K[0], 1e-6f), fy = fmaxf(K[4], 1e-6f);
        float cx = K[2], cy = K[5];
        float xc = (xs - cx) * z / fx;
        float yc = (ys - cy) * z / fy;

        const float* T = Tlc + b * 16;
        float lx = T[0] * xc + T[1] * yc + T[2]  * z + T[3];
        float ly = T[4] * xc + T[5] * yc + T[6]  * z + T[7];
        float lz = T[8] * xc + T[9] * yc + T[10] * z + T[11];

        int xi = (int)floorf((lx + 51.2f) * 2.5f);
        int yi = (int)floorf((ly + 51.2f) * 2.5f);
        bool inb = (xi >= 0) && (xi < NXV) && (yi >= 0) && (yi < NYV) &&
                   (lz >= -5.f) && (lz < 3.f);
        float op = sprm[0];
        float bw = (op >= 0.05f && inb) ? op : 0.f;
        sprm[1] = bw;
        sprm[2] = __int_as_float(xi);
        sprm[3] = __int_as_float(yi);
    }
    __syncthreads();

    float bw = sprm[1];
    if (bw <= 0.f) return;
    int xi = __float_as_int(sprm[2]);
    int yi = __float_as_int(sprm[3]);

    #pragma unroll
    for (int tap = 0; tap < 9; tap++) {
        int dy = tap / 3 - 1;
        int dx = tap % 3 - 1;
        int ty = yi + dy;
        int tx = xi + dx;
        if ((unsigned)tx >= (unsigned)NXV || (unsigned)ty >= (unsigned)NYV) continue;
        float kwv = expf(-(float)(dx * dx + dy * dy) * (1.f / 1.28f));
        float sw = bw * kwv;
        int vox = b * SV + ty * NXV + tx;
        if (tid < OUTC) atomicAdd(&g_canvas[(size_t)vox * OUTC + tid], sfeat[tid] * sw);
        if (tid == OUTC) atomicAdd(&g_wacc[vox], sw);
    }
}

// ---------------- normalize + transpose (pix, C) -> (B, C, NY, NX) ----------------
__global__ void finalize_kernel(float* __restrict__ out)
{
    __shared__ float tile[OUTC][33];
    int gp  = blockIdx.x * 32;
    int tid = threadIdx.x;

    for (int i = tid; i < 32 * OUTC; i += 256) {
        int p = i >> 6;
        int c = i & 63;
        float wv  = g_wacc[gp + p];
        float inv = (wv > 0.f) ? (1.f / fmaxf(wv, 1e-6f)) : 0.f;
        tile[c][p] = g_canvas[(size_t)(gp + p) * OUTC + c] * inv;
    }
    __syncthreads();

    int b  = gp >> 16;
    int p0 = gp & 65535;
    for (int i = tid; i < OUTC * 32; i += 256) {
        int c = i >> 5;
        int x = i & 31;
        out[(((b * OUTC) + c) << 16) + p0 + x] = tile[c][x];
    }
}

// ---------------- launch ----------------
extern "C" void kernel_launch(void* const* d_in, const int* in_sizes, int n_in,
                              void* d_out, int out_size)
{
    const float* images = (const float*)d_in[0];
    const float* camK   = (const float*)d_in[1];
    const float* Tlc    = (const float*)d_in[2];
    const float* w1 = (const float*)d_in[3];
    const float* s1 = (const float*)d_in[4];
    const float* b1 = (const float*)d_in[5];
    const float* w2 = (const float*)d_in[6];
    const float* s2 = (const float*)d_in[7];
    const float* b2 = (const float*)d_in[8];
    const float* w3 = (const float*)d_in[9];
    const float* s3 = (const float*)d_in[10];
    const float* b3 = (const float*)d_in[11];
    const float* w4 = (const float*)d_in[12];
    const float* s4 = (const float*)d_in[13];
    const float* b4 = (const float*)d_in[14];
    const float* fw1 = (const float*)d_in[15];
    const float* fs1 = (const float*)d_in[16];
    const float* fb1 = (const float*)d_in[17];
    const float* fw2 = (const float*)d_in[18];
    const float* fb2 = (const float*)d_in[19];
    const float* dw  = (const float*)d_in[20];
    const float* db  = (const float*)d_in[21];
    const float* ow  = (const float*)d_in[22];
    const float* ob  = (const float*)d_in[23];
    const int* imgh  = (const int*)d_in[24];
    const int* imgw  = (const int*)d_in[25];
    float* out = (float*)d_out;

    float* x1;  cudaGetSymbolAddress((void**)&x1,  g_x1);
    float* x2;  cudaGetSymbolAddress((void**)&x2,  g_x2);
    float* x3;  cudaGetSymbolAddress((void**)&x3,  g_x3);
    float* x4;  cudaGetSymbolAddress((void**)&x4,  g_x4);
    float* fhp; cudaGetSymbolAddress((void**)&fhp, g_fh);
    float* wb2; cudaGetSymbolAddress((void**)&wb2, g_wb2);
    float* wb3; cudaGetSymbolAddress((void**)&wb3, g_wb3);
    float* wb4; cudaGetSymbolAddress((void**)&wb4, g_wb4);
    float* wb5; cudaGetSymbolAddress((void**)&wb5, g_wb5);

    cudaFuncSetAttribute((const void*)conv_gemm_db<C1, C2, 2, H1, W1, H2, W2>,
                         cudaFuncAttributeMaxDynamicSharedMemorySize, SMEMDB);
    cudaFuncSetAttribute((const void*)conv_gemm_db<C2, C3, 2, H2, W2, H3, W3>,
                         cudaFuncAttributeMaxDynamicSharedMemorySize, SMEMDB);
    cudaFuncSetAttribute((const void*)conv_gemm_db<C3, C4, 2, H3, W3, HF, WF>,
                         cudaFuncAttributeMaxDynamicSharedMemorySize, SMEMDB);
    cudaFuncSetAttribute((const void*)conv_gemm_db<C4, C4, 1, HF, WF, HF, WF>,
                         cudaFuncAttributeMaxDynamicSharedMemorySize, SMEMDB);

    wprep1<<<(36 * 32 + 255) / 256, 256>>>(w1);
    wprepKO<<<(288 * 64 + 255) / 256, 256>>>(w2, wb2, 32, 32, 64, 288 * 64);
    wprepKO<<<(576 * 128 + 255) / 256, 256>>>(w3, wb3, 64, 64, 128, 576 * 128);
    wprepKO<<<(1152 * 128 + 255) / 256, 256>>>(w4, wb4, 128, 128, 128, 1152 * 128);
    wprepKO<<<(1152 * 128 + 255) / 256, 256>>>(fw1, wb5, 128, 128, 128, 1152 * 128);

    im2nhwc<<<(B_ * IMG_H * IMG_W + 255) / 256, 256>>>(images);
    zero_kernel<<<2048, 256>>>();

    conv1_kernel<<<B_ * H1 * W1 / 256, 256>>>(s1, b1);

    conv_gemm_db<C1, C2, 2, H1, W1, H2, W2>
        <<<dim3(B_ * H2 * W2 / 128, 1), 256, SMEMDB>>>(x1, wb2, s2, b2, x2);
    conv_gemm_db<C2, C3, 2, H2, W2, H3, W3>
        <<<dim3(B_ * H3 * W3 / 128, 2), 256, SMEMDB>>>(x2, wb3, s3, b3, x3);
    conv_gemm_db<C3, C4, 2, H3, W3, HF, WF>
        <<<dim3(B_ * HF * WF / 128, 2), 256, SMEMDB>>>(x3, wb4, s4, b4, x4);
    conv_gemm_db<C4, C4, 1, HF, WF, HF, WF>
        <<<dim3(B_ * HF * WF / 128, 2), 256, SMEMDB>>>(x4, wb5, fs1, fb1, fhp);

    heads_splat<<<B_ * HF * WF, 128>>>(x4, fhp, fw2, fb2, dw, db, ow, ob,
                                       camK, Tlc, imgh, imgw);

    finalize_kernel<<<B_ * SV / 32, 256>>>(out);
}